// round 13
// baseline (speedup 1.0000x reference)
#include <cuda_runtime.h>
#include <cuda_fp16.h>
#include <cstdint>

static constexpr int NB = 8;
static constexpr int NC = 256;
static constexpr int NH = 160;
static constexpr int NW = 160;
static constexpr int NHW = NH * NW;           // 25600
static constexpr int TILE_N = 64;
static constexpr int NTILES = NHW / TILE_N;   // 400
static constexpr float BN_EPS = 1e-5f;

// dynamic smem (u32 units): X double buffer, 2 stages x 2560 (2 subs of 1280)
static constexpr int DSMEM_U32 = 5120;        // 20 KB

// ---------------- scratch (static device globals) --------------------------
__device__ __half g_xalh[(size_t)NB * NC * NHW];   // fp16 aligned activations
__device__ uint32_t g_wfragA[256 * 128];  // W in mma-A-fragment layout (128 KB)
__device__ float g_bias[NC];
__device__ float g_ppart[(size_t)NB * NTILES * NC * 5];  // pool partials 16.4MB
__device__ float g_gsum[NB * NC];
__device__ float g_gmax[NB * NC];
__device__ float g_lsum[NB * NC * 16];
__device__ float g_ca[NB * NC];
__device__ float g_sf[NB * 2 * NHW];
__device__ float g_o1[NB * 16 * NHW];
__device__ float g_sampled[NB * 2 * NHW];
__device__ float g_sa[NB * NHW];
__device__ float g_wavg[2 * 16 * 9];
__device__ float g_bavg[2];

__device__ __forceinline__ float sigmoidf_(float x) {
    return 1.f / (1.f + __expf(-x));
}
__device__ __forceinline__ uint32_t packh(__half a, __half b) {
    __half2 t = __halves2half2(a, b);     // low = a
    return *reinterpret_cast<uint32_t*>(&t);
}
__device__ __forceinline__ float2 h2f2(uint32_t u) {
    return __half22float2(*reinterpret_cast<__half2*>(&u));
}
__device__ __forceinline__ int cellAt(int p) {
    const int h = p / NW, w = p - h * NW;
    return (h / 40) * 4 + (w / 40);
}
__device__ __forceinline__ void mma16816h(float* c, uint32_t a0, uint32_t a1,
                                          uint32_t a2, uint32_t a3,
                                          uint32_t b0, uint32_t b1) {
    asm volatile(
        "mma.sync.aligned.m16n8k16.row.col.f32.f16.f16.f32 "
        "{%0,%1,%2,%3}, {%4,%5,%6,%7}, {%8,%9}, {%0,%1,%2,%3};"
        : "+f"(c[0]), "+f"(c[1]), "+f"(c[2]), "+f"(c[3])
        : "r"(a0), "r"(a1), "r"(a2), "r"(a3), "r"(b0), "r"(b1));
}
__device__ __forceinline__ void ldsm4(uint32_t* d, uint32_t addr) {
    asm volatile(
        "ldmatrix.sync.aligned.m8n8.x4.shared.b16 {%0,%1,%2,%3}, [%4];"
        : "=r"(d[0]), "=r"(d[1]), "=r"(d[2]), "=r"(d[3]) : "r"(addr));
}

// ---------------------------------------------------------------------------
// Kernel 0: W pack (A-fragment layout) + averaged offset-conv2 weights
// Blocks 0..127: wpack (256 threads used). Block 128: prep.
// ---------------------------------------------------------------------------
__global__ __launch_bounds__(288) void wprep_kernel(
    const float* __restrict__ w, const float* __restrict__ g,
    const float* __restrict__ bb, const float* __restrict__ m,
    const float* __restrict__ v,
    const float* __restrict__ off_w2, const float* __restrict__ off_b2)
{
    if (blockIdx.x < 128) {
        if (threadIdx.x >= 256) return;
        const int id = blockIdx.x * 256 + threadIdx.x;   // 0..32767
        const int co = id >> 7, kp = id & 127;
        const float sc = g[co] * rsqrtf(v[co] + BN_EPS);
        const float w0 = w[co * 256 + 2 * kp] * sc;
        const float w1 = w[co * 256 + 2 * kp + 1] * sc;
        const uint32_t packed = packh(__float2half_rn(w0), __float2half_rn(w1));
        const int cb = co >> 4, mm = co & 15;
        const int kb = kp >> 3, kl = kp & 7;
        const int lane = (mm & 7) * 4 + (kl & 3);
        const int i = ((mm >> 3) & 1) | (((kl >> 2) & 1) << 1);
        g_wfragA[(((cb * 16) + kb) * 32 + lane) * 4 + i] = packed;
        if (kp == 0) g_bias[co] = bb[co] - m[co] * sc;
    } else {
        const int i = threadIdx.x;
        if (i < 288) {
            const int d = i / 144, rest = i % 144;
            float s = 0.f;
            for (int j = 0; j < 49; j++) s += off_w2[(d * 49 + j) * 144 + rest];
            g_wavg[i] = s * (1.f / 49.f);
        }
        if (i < 2) {
            float s = 0.f;
            for (int j = 0; j < 49; j++) s += off_b2[i * 49 + j];
            g_bavg[i] = s * (1.f / 49.f);
        }
    }
}

// ---------------------------------------------------------------------------
// Kernel 1: tensor-core GEMM, CTA = [256 co x 64 px], K=256 in 4 chunks of 64.
//   W via direct uint4 LDG of A fragments; X double-buffered smem.
//   Epilogue: bias + SiLU + fp16 store + POOL PARTIALS (sum/max/3 cells).
// ---------------------------------------------------------------------------
__global__ void __launch_bounds__(256, 2) gemm_kernel(const float* __restrict__ X)
{
    extern __shared__ uint32_t sm[];
    const int tile = blockIdx.x, b = blockIdx.y;
    const int tileBase = tile * TILE_N;
    const int t = threadIdx.x, lane = t & 31, warp = t >> 5;   // warp = warpM 0..7
    const int q = lane >> 2, r = lane & 3;
    const float* Xb = X + (size_t)b * NC * NHW + tileBase;
    const int kq = t & 31, pg = t >> 5;

    const uint32_t smBase = (uint32_t)__cvta_generic_to_shared(sm);
    const uint32_t bOff = (uint32_t)((((lane & 16) ? 8 : 0) + (lane & 7)) * 20
                                     + ((lane & 8) ? 4 : 0));

    float acc[2][8][4];
    #pragma unroll
    for (int i = 0; i < 2; i++)
        #pragma unroll
        for (int j = 0; j < 8; j++)
            #pragma unroll
            for (int k = 0; k < 4; k++) acc[i][j][k] = 0.f;

    float4 xr0, xr1, xr2, xr3;

    auto ldgX = [&](int c) {
        const float* x0 = Xb + (size_t)(c * 64 + 2 * kq) * NHW + pg * 8;
        xr0 = *(const float4*)x0;         xr1 = *(const float4*)(x0 + 4);
        xr2 = *(const float4*)(x0 + NHW); xr3 = *(const float4*)(x0 + NHW + 4);
    };
    auto stsX = [&](int sx) {
        float e0[8] = {xr0.x, xr0.y, xr0.z, xr0.w, xr1.x, xr1.y, xr1.z, xr1.w};
        float e1[8] = {xr2.x, xr2.y, xr2.z, xr2.w, xr3.x, xr3.y, xr3.z, xr3.w};
        const int base = sx * 2560 + (kq >> 4) * 1280;
        const int kpc = kq & 15;
        #pragma unroll
        for (int j = 0; j < 8; j++) {
            sm[base + (pg * 8 + j) * 20 + kpc] =
                packh(__float2half_rn(e0[j]), __float2half_rn(e1[j]));
        }
    };

    const uint32_t wfBase = (uint32_t)(warp * 2 * 16 * 128 + lane * 4);

    // ---- prologue ----
    ldgX(0);
    stsX(0);
    ldgX(1);
    __syncthreads();

    for (int c = 0; c < 4; c++) {
        if (c < 3) stsX((c + 1) & 1);
        if (c < 2) ldgX(c + 2);

        const uint32_t xStgBase = smBase + (uint32_t)((c & 1) * 2560) * 4u;
        #pragma unroll
        for (int sub = 0; sub < 2; sub++) {
            const uint32_t xhS = xStgBase + (uint32_t)(sub * 1280) * 4u;
            #pragma unroll
            for (int ks = 0; ks < 2; ks++) {
                const int kb = c * 4 + sub * 2 + ks;
                uint4 A0 = *(const uint4*)&g_wfragA[wfBase + (0 * 16 + kb) * 128];
                uint4 A1 = *(const uint4*)&g_wfragA[wfBase + (1 * 16 + kb) * 128];
                #pragma unroll
                for (int np = 0; np < 4; np++) {
                    uint32_t B0[4];
                    ldsm4(B0, xhS + (bOff + np * 320 + ks * 8) * 4u);
                    #pragma unroll
                    for (int j = 0; j < 2; j++) {
                        mma16816h(acc[0][np * 2 + j], A0.x, A0.y, A0.z, A0.w,
                                  B0[2 * j], B0[2 * j + 1]);
                        mma16816h(acc[1][np * 2 + j], A1.x, A1.y, A1.z, A1.w,
                                  B0[2 * j], B0[2 * j + 1]);
                    }
                }
            }
        }
        __syncthreads();
    }

    // ---- cell breakpoints for this tile (<=2 transitions over 64 px) ----
    int bp1 = 64, bp2 = 64;
    {
        int prev = cellAt(tileBase);
        for (int p2 = 1; p2 < 64; p2++) {
            int cc2 = cellAt(tileBase + p2);
            if (cc2 != prev) {
                if (bp1 == 64) bp1 = p2; else bp2 = p2;
                prev = cc2;
            }
        }
    }

    // ---- epilogue: bias + SiLU + fp16 store + pool partials ----
    const size_t ctaP = ((size_t)b * NTILES + tile) * NC;
    #pragma unroll
    for (int mt = 0; mt < 2; mt++) {
        const int co0 = warp * 32 + mt * 16 + q;
        const int co1 = co0 + 8;
        const float tb0 = g_bias[co0], tb1 = g_bias[co1];
        __half* y0 = g_xalh + ((size_t)b * NC + co0) * NHW + tileBase;
        __half* y1 = g_xalh + ((size_t)b * NC + co1) * NHW + tileBase;
        float s0 = 0.f, m0 = -1e30f, cA0 = 0.f, cB0 = 0.f, cC0 = 0.f;
        float s1 = 0.f, m1 = -1e30f, cA1 = 0.f, cB1 = 0.f, cC1 = 0.f;
        #pragma unroll
        for (int nt = 0; nt < 8; nt++) {
            const int pix = nt * 8 + 2 * r;
            const int sl0 = (pix >= bp1) + (pix >= bp2);
            const int sl1 = ((pix + 1) >= bp1) + ((pix + 1) >= bp2);
            float v0 = acc[mt][nt][0] + tb0, v1 = acc[mt][nt][1] + tb0;
            float v2 = acc[mt][nt][2] + tb1, v3 = acc[mt][nt][3] + tb1;
            const float z0 = v0 * sigmoidf_(v0), z1 = v1 * sigmoidf_(v1);
            const float z2 = v2 * sigmoidf_(v2), z3 = v3 * sigmoidf_(v3);
            *(__half2*)&y0[pix] = __floats2half2_rn(z0, z1);
            *(__half2*)&y1[pix] = __floats2half2_rn(z2, z3);
            s0 += z0 + z1;  m0 = fmaxf(m0, fmaxf(z0, z1));
            s1 += z2 + z3;  m1 = fmaxf(m1, fmaxf(z2, z3));
            if (sl0 == 0) { cA0 += z0; cA1 += z2; }
            else if (sl0 == 1) { cB0 += z0; cB1 += z2; }
            else { cC0 += z0; cC1 += z2; }
            if (sl1 == 0) { cA0 += z1; cA1 += z3; }
            else if (sl1 == 1) { cB0 += z1; cB1 += z3; }
            else { cC0 += z1; cC1 += z3; }
        }
        #pragma unroll
        for (int o = 1; o <= 2; o <<= 1) {
            s0 += __shfl_xor_sync(0xffffffffu, s0, o);
            s1 += __shfl_xor_sync(0xffffffffu, s1, o);
            m0 = fmaxf(m0, __shfl_xor_sync(0xffffffffu, m0, o));
            m1 = fmaxf(m1, __shfl_xor_sync(0xffffffffu, m1, o));
            cA0 += __shfl_xor_sync(0xffffffffu, cA0, o);
            cB0 += __shfl_xor_sync(0xffffffffu, cB0, o);
            cC0 += __shfl_xor_sync(0xffffffffu, cC0, o);
            cA1 += __shfl_xor_sync(0xffffffffu, cA1, o);
            cB1 += __shfl_xor_sync(0xffffffffu, cB1, o);
            cC1 += __shfl_xor_sync(0xffffffffu, cC1, o);
        }
        if (r == 0) {
            float* p0 = &g_ppart[(ctaP + co0) * 5];
            p0[0] = s0; p0[1] = m0; p0[2] = cA0; p0[3] = cB0; p0[4] = cC0;
            float* p1 = &g_ppart[(ctaP + co1) * 5];
            p1[0] = s1; p1[1] = m1; p1[2] = cA1; p1[3] = cB1; p1[4] = cC1;
        }
    }
}

// ---------------------------------------------------------------------------
// Kernel 2: reduce pool partials -> g_gsum / g_gmax / g_lsum  (deterministic)
// One block per (b, co), 128 threads.
// ---------------------------------------------------------------------------
__global__ __launch_bounds__(128) void pool_reduce_kernel() {
    const int blk = blockIdx.x;             // b*256 + co
    const int b = blk >> 8, co = blk & 255;
    const int tid = threadIdx.x;

    __shared__ float sc[128][17];           // per-thread 16 cells (padded)
    __shared__ float ss[128], sm2[128];
    #pragma unroll
    for (int i = 0; i < 16; i++) sc[tid][i] = 0.f;

    float s = 0.f, m = -1e30f;
    for (int tIdx = tid; tIdx < NTILES; tIdx += 128) {
        const float* pp = &g_ppart[(((size_t)b * NTILES + tIdx) * NC + co) * 5];
        s += pp[0];
        m = fmaxf(m, pp[1]);
        // tile cell ids
        const int base = tIdx * TILE_N;
        int prev = cellAt(base), cA = prev, cB = -1, cC = -1;
        for (int p2 = 1; p2 < 64; p2++) {
            int cc2 = cellAt(base + p2);
            if (cc2 != prev) {
                if (cB < 0) cB = cc2; else cC = cc2;
                prev = cc2;
            }
        }
        sc[tid][cA] += pp[2];
        if (cB >= 0) sc[tid][cB] += pp[3];
        if (cC >= 0) sc[tid][cC] += pp[4];
    }
    ss[tid] = s; sm2[tid] = m;
    __syncthreads();
    for (int o = 64; o > 0; o >>= 1) {
        if (tid < o) {
            ss[tid] += ss[tid + o];
            sm2[tid] = fmaxf(sm2[tid], sm2[tid + o]);
        }
        __syncthreads();
    }
    if (tid == 0) { g_gsum[blk] = ss[0]; g_gmax[blk] = sm2[0]; }
    if (tid < 16) {
        float v = 0.f;
        for (int i = 0; i < 128; i++) v += sc[i][tid];
        g_lsum[blk * 16 + tid] = v;
    }
}

// ---------------------------------------------------------------------------
// Kernel 4: channel attention -> g_ca
// ---------------------------------------------------------------------------
__global__ __launch_bounds__(256) void ca_kernel(
    const float* __restrict__ mlp_w1, const float* __restrict__ mlp_w2,
    const float* __restrict__ loc_w1, const float* __restrict__ loc_w2,
    const float* __restrict__ fusion_w)
{
    const int b = blockIdx.x, tid = threadIdx.x;
    __shared__ float avg[256], mxv[256];
    __shared__ float h1[32], hpart[32][8], hcell[16][16], hbar[16];

    avg[tid] = g_gsum[b * NC + tid] * (1.f / (float)NHW);
    mxv[tid] = g_gmax[b * NC + tid];
    __syncthreads();

    {
        const int m = tid >> 3, part = tid & 7;
        const int mm = m & 15;
        const float* src = (m < 16) ? avg : mxv;
        float a = 0.f;
        #pragma unroll 8
        for (int c = part * 32; c < part * 32 + 32; c++)
            a += mlp_w1[mm * NC + c] * src[c];
        hpart[m][part] = a;
    }
    {
        const int cell = tid >> 4, m2 = tid & 15;
        float a = 0.f;
        #pragma unroll 8
        for (int c = 0; c < NC; c++)
            a += loc_w1[m2 * NC + c] * g_lsum[(b * NC + c) * 16 + cell];
        hcell[cell][m2] = fmaxf(a * (1.f / 1600.f), 0.f);
    }
    __syncthreads();
    if (tid < 32) {
        float a = 0.f;
        #pragma unroll
        for (int p = 0; p < 8; p++) a += hpart[tid][p];
        h1[tid] = fmaxf(a, 0.f);
    }
    if (tid >= 32 && tid < 48) {
        float s = 0.f;
        #pragma unroll
        for (int cell = 0; cell < 16; cell++) s += hcell[cell][tid - 32];
        hbar[tid - 32] = s * (1.f / 16.f);
    }
    __syncthreads();

    float ga = 0.f, la = 0.f;
    #pragma unroll
    for (int m = 0; m < 16; m++) {
        ga += mlp_w2[tid * 16 + m] * (h1[m] + h1[16 + m]);
        la += loc_w2[tid * 16 + m] * hbar[m];
    }
    const float alpha = sigmoidf_(fusion_w[0]);
    g_ca[b * NC + tid] = sigmoidf_(alpha * ga + (1.f - alpha) * la);
}

// ---------------------------------------------------------------------------
// Kernel 5: sf = [mean_c(ca*x), max_c(ca*x)]  (fp16 input, 4 px / thread)
// ---------------------------------------------------------------------------
__global__ __launch_bounds__(256) void sf_kernel() {
    const int b = blockIdx.y;
    const int p4 = blockIdx.x * 256 + threadIdx.x;       // 0..6399
    const __half* xb = g_xalh + (size_t)b * NC * NHW;
    const float* cab = g_ca + b * NC;
    float4 s = make_float4(0.f, 0.f, 0.f, 0.f);
    float4 mx = make_float4(-1e30f, -1e30f, -1e30f, -1e30f);
    #pragma unroll 4
    for (int c = 0; c < NC; c++) {
        const float cc = cab[c];
        uint2 u = *(const uint2*)(xb + (size_t)c * NHW + p4 * 4);
        float2 f0 = h2f2(u.x), f1 = h2f2(u.y);
        float v0 = cc * f0.x, v1 = cc * f0.y, v2 = cc * f1.x, v3 = cc * f1.y;
        s.x += v0; s.y += v1; s.z += v2; s.w += v3;
        mx.x = fmaxf(mx.x, v0); mx.y = fmaxf(mx.y, v1);
        mx.z = fmaxf(mx.z, v2); mx.w = fmaxf(mx.w, v3);
    }
    const float inv = 1.f / (float)NC;
    s.x *= inv; s.y *= inv; s.z *= inv; s.w *= inv;
    ((float4*)(g_sf + (size_t)b * 2 * NHW))[p4] = s;
    ((float4*)(g_sf + (size_t)b * 2 * NHW + NHW))[p4] = mx;
}

// ---------------------------------------------------------------------------
// Kernel 6: offset conv1: 3x3, 2->16 + BN + ReLU
// ---------------------------------------------------------------------------
__global__ __launch_bounds__(256) void off1_kernel(
    const float* __restrict__ w1, const float* __restrict__ gg,
    const float* __restrict__ bt, const float* __restrict__ mm,
    const float* __restrict__ vv)
{
    const int p = blockIdx.x * blockDim.x + threadIdx.x;
    const int co = blockIdx.y, b = blockIdx.z;
    const int h = p / NW, w = p % NW;
    const float* sfb = g_sf + (size_t)b * 2 * NHW;
    float acc = 0.f;
    #pragma unroll
    for (int ci = 0; ci < 2; ci++) {
        #pragma unroll
        for (int ky = 0; ky < 3; ky++) {
            const int hy = h + ky - 1;
            if (hy < 0 || hy >= NH) continue;
            #pragma unroll
            for (int kx = 0; kx < 3; kx++) {
                const int wx = w + kx - 1;
                if (wx < 0 || wx >= NW) continue;
                acc += w1[((co * 2 + ci) * 3 + ky) * 3 + kx] *
                       sfb[ci * NHW + hy * NW + wx];
            }
        }
    }
    const float sc = gg[co] * rsqrtf(vv[co] + BN_EPS);
    const float tb = bt[co] - mm[co] * sc;
    g_o1[((size_t)b * 16 + co) * NHW + p] = fmaxf(acc * sc + tb, 0.f);
}

// ---------------------------------------------------------------------------
// Kernel 7: averaged offset conv2 + tanh*0.5 + grid + bilinear sample
// ---------------------------------------------------------------------------
__global__ __launch_bounds__(256) void off2_sample_kernel() {
    const int b = blockIdx.y;
    const int p = blockIdx.x * blockDim.x + threadIdx.x;
    const int h = p / NW, w = p % NW;
    const float* o1b = g_o1 + (size_t)b * 16 * NHW;

    float off[2];
    #pragma unroll
    for (int d = 0; d < 2; d++) {
        float acc = g_bavg[d];
        for (int ci = 0; ci < 16; ci++) {
            #pragma unroll
            for (int ky = 0; ky < 3; ky++) {
                const int hy = h + ky - 1;
                if (hy < 0 || hy >= NH) continue;
                #pragma unroll
                for (int kx = 0; kx < 3; kx++) {
                    const int wx = w + kx - 1;
                    if (wx < 0 || wx >= NW) continue;
                    acc += g_wavg[(d * 16 + ci) * 9 + ky * 3 + kx] *
                           o1b[(size_t)ci * NHW + hy * NW + wx];
                }
            }
        }
        off[d] = tanhf(acc) * 0.5f;
    }

    const float bx = -1.f + 2.f * (float)w / 159.f;
    const float by = -1.f + 2.f * (float)h / 159.f;
    const float gx = fminf(fmaxf(bx + off[0], -1.f), 1.f);
    const float gy = fminf(fmaxf(by + off[1], -1.f), 1.f);

    const float fx = (gx + 1.f) * ((float)NW * 0.5f) - 0.5f;
    const float fy = (gy + 1.f) * ((float)NH * 0.5f) - 0.5f;
    const float x0f = floorf(fx), y0f = floorf(fy);
    const int x0 = (int)x0f, y0 = (int)y0f;
    const float wx = fx - x0f, wy = fy - y0f;

    const float* sfb = g_sf + (size_t)b * 2 * NHW;
    float out0 = 0.f, out1 = 0.f;
    #pragma unroll
    for (int dy = 0; dy < 2; dy++) {
        const int yy = y0 + dy;
        if (yy < 0 || yy >= NH) continue;
        const float wgy = dy ? wy : (1.f - wy);
        #pragma unroll
        for (int dx = 0; dx < 2; dx++) {
            const int xx = x0 + dx;
            if (xx < 0 || xx >= NW) continue;
            const float wt = wgy * (dx ? wx : (1.f - wx));
            out0 += wt * sfb[yy * NW + xx];
            out1 += wt * sfb[NHW + yy * NW + xx];
        }
    }
    g_sampled[(size_t)b * 2 * NHW + p] = out0;
    g_sampled[(size_t)b * 2 * NHW + NHW + p] = out1;
}

// ---------------------------------------------------------------------------
// Kernel 8: 7x7 conv (2->1) over sampled + sigmoid -> g_sa
// ---------------------------------------------------------------------------
__global__ __launch_bounds__(256) void sa_kernel(const float* __restrict__ attn_w) {
    const int b = blockIdx.y;
    const int p = blockIdx.x * blockDim.x + threadIdx.x;
    const int h = p / NW, w = p % NW;
    const float* sm = g_sampled + (size_t)b * 2 * NHW;
    float acc = 0.f;
    #pragma unroll
    for (int ci = 0; ci < 2; ci++) {
        #pragma unroll
        for (int ky = 0; ky < 7; ky++) {
            const int hy = h + ky - 3;
            if (hy < 0 || hy >= NH) continue;
            #pragma unroll
            for (int kx = 0; kx < 7; kx++) {
                const int wx = w + kx - 3;
                if (wx < 0 || wx >= NW) continue;
                acc += attn_w[(ci * 7 + ky) * 7 + kx] *
                       sm[ci * NHW + hy * NW + wx];
            }
        }
    }
    g_sa[b * NHW + p] = sigmoidf_(acc);
}

// ---------------------------------------------------------------------------
// Kernel 9: out = sa * ca * x_aligned  (fp16 xal, 8 elems / thread)
// ---------------------------------------------------------------------------
__global__ __launch_bounds__(256) void final_kernel(float* __restrict__ out) {
    const unsigned idx8 = blockIdx.x * blockDim.x + threadIdx.x;
    const unsigned total8 = (unsigned)NB * NC * NHW / 8;
    if (idx8 >= total8) return;
    const unsigned e = idx8 * 8;
    const unsigned p = e % NHW;
    const unsigned c = (e / NHW) % NC;
    const unsigned b = e / (NHW * NC);
    uint4 u = *(const uint4*)(g_xalh + e);
    float2 f0 = h2f2(u.x), f1 = h2f2(u.y), f2 = h2f2(u.z), f3 = h2f2(u.w);
    const float4 sa0 = *reinterpret_cast<const float4*>(&g_sa[b * NHW + p]);
    const float4 sa1 = *reinterpret_cast<const float4*>(&g_sa[b * NHW + p + 4]);
    const float cc = g_ca[b * NC + c];
    float4 r0, r1;
    r0.x = f0.x * sa0.x * cc;  r0.y = f0.y * sa0.y * cc;
    r0.z = f1.x * sa0.z * cc;  r0.w = f1.y * sa0.w * cc;
    r1.x = f2.x * sa1.x * cc;  r1.y = f2.y * sa1.y * cc;
    r1.z = f3.x * sa1.z * cc;  r1.w = f3.y * sa1.w * cc;
    *reinterpret_cast<float4*>(&out[e]) = r0;
    *reinterpret_cast<float4*>(&out[e + 4]) = r1;
}

// ---------------------------------------------------------------------------
extern "C" void kernel_launch(void* const* d_in, const int* in_sizes, int n_in,
                              void* d_out, int out_size) {
    const float* x       = (const float*)d_in[0];
    const float* align_w = (const float*)d_in[1];
    const float* align_g = (const float*)d_in[2];
    const float* align_b = (const float*)d_in[3];
    const float* align_m = (const float*)d_in[4];
    const float* align_v = (const float*)d_in[5];
    const float* mlp_w1  = (const float*)d_in[6];
    const float* mlp_w2  = (const float*)d_in[7];
    const float* loc_w1  = (const float*)d_in[8];
    const float* loc_w2  = (const float*)d_in[9];
    const float* fusion  = (const float*)d_in[10];
    const float* off_w1  = (const float*)d_in[11];
    const float* off_g   = (const float*)d_in[12];
    const float* off_bt  = (const float*)d_in[13];
    const float* off_m   = (const float*)d_in[14];
    const float* off_v   = (const float*)d_in[15];
    const float* off_w2  = (const float*)d_in[16];
    const float* off_b2  = (const float*)d_in[17];
    const float* attn_w  = (const float*)d_in[18];
    float* out = (float*)d_out;

    wprep_kernel<<<129, 288>>>(align_w, align_g, align_b, align_m, align_v,
                               off_w2, off_b2);

    dim3 gGemm(NTILES, NB);
    gemm_kernel<<<gGemm, 256, DSMEM_U32 * 4>>>(x);

    pool_reduce_kernel<<<NB * NC, 128>>>();
    ca_kernel<<<NB, 256>>>(mlp_w1, mlp_w2, loc_w1, loc_w2, fusion);

    dim3 gPix4(NHW / 4 / 256, NB);
    sf_kernel<<<gPix4, 256>>>();

    dim3 gPix(NHW / 256, NB);
    dim3 gOff1(NHW / 256, 16, NB);
    off1_kernel<<<gOff1, 256>>>(off_w1, off_g, off_bt, off_m, off_v);
    off2_sample_kernel<<<gPix, 256>>>();
    sa_kernel<<<gPix, 256>>>(attn_w);

    const unsigned total8 = (unsigned)NB * NC * NHW / 8;
    final_kernel<<<(total8 + 255) / 256, 256>>>(out);
}

// round 14
// speedup vs baseline: 1.2891x; 1.2891x over previous
#include <cuda_runtime.h>
#include <cuda_fp16.h>
#include <cstdint>

static constexpr int NB = 8;
static constexpr int NC = 256;
static constexpr int NH = 160;
static constexpr int NW = 160;
static constexpr int NHW = NH * NW;           // 25600
static constexpr int TILE_N = 64;
static constexpr int NTILES = NHW / TILE_N;   // 400
static constexpr float BN_EPS = 1e-5f;

// dynamic smem (u32 units): X double buffer, 2 stages x 2560 (2 subs of 1280)
static constexpr int DSMEM_U32 = 5120;        // 20 KB

// ---------------- scratch (static device globals) --------------------------
__device__ __half g_xalh[(size_t)NB * NC * NHW];   // fp16 aligned activations
__device__ uint32_t g_wfragA[256 * 128];  // W in mma-A-fragment layout (128 KB)
__device__ float g_bias[NC];
__device__ float g_gsum[NB * NC];
__device__ float g_gmax[NB * NC];
__device__ float g_lsum[NB * NC * 16];
__device__ float g_ca[NB * NC];
__device__ float g_sf[NB * 2 * NHW];
__device__ float g_o1[NB * 16 * NHW];
__device__ float g_sampled[NB * 2 * NHW];
__device__ float g_sa[NB * NHW];
__device__ float g_wavg[2 * 16 * 9];
__device__ float g_bavg[2];

__device__ __forceinline__ float sigmoidf_(float x) {
    return 1.f / (1.f + __expf(-x));
}
__device__ __forceinline__ uint32_t packh(__half a, __half b) {
    __half2 t = __halves2half2(a, b);     // low = a
    return *reinterpret_cast<uint32_t*>(&t);
}
__device__ __forceinline__ float2 h2f2(uint32_t u) {
    return __half22float2(*reinterpret_cast<__half2*>(&u));
}
__device__ __forceinline__ void mma16816h(float* c, uint32_t a0, uint32_t a1,
                                          uint32_t a2, uint32_t a3,
                                          uint32_t b0, uint32_t b1) {
    asm volatile(
        "mma.sync.aligned.m16n8k16.row.col.f32.f16.f16.f32 "
        "{%0,%1,%2,%3}, {%4,%5,%6,%7}, {%8,%9}, {%0,%1,%2,%3};"
        : "+f"(c[0]), "+f"(c[1]), "+f"(c[2]), "+f"(c[3])
        : "r"(a0), "r"(a1), "r"(a2), "r"(a3), "r"(b0), "r"(b1));
}
__device__ __forceinline__ void ldsm4(uint32_t* d, uint32_t addr) {
    asm volatile(
        "ldmatrix.sync.aligned.m8n8.x4.shared.b16 {%0,%1,%2,%3}, [%4];"
        : "=r"(d[0]), "=r"(d[1]), "=r"(d[2]), "=r"(d[3]) : "r"(addr));
}

// ---------------------------------------------------------------------------
// Kernel 0: W pack (A-fragment layout) + averaged offset-conv2 weights
// Blocks 0..127: wpack. Block 128: prep.
// ---------------------------------------------------------------------------
__global__ __launch_bounds__(288) void wprep_kernel(
    const float* __restrict__ w, const float* __restrict__ g,
    const float* __restrict__ bb, const float* __restrict__ m,
    const float* __restrict__ v,
    const float* __restrict__ off_w2, const float* __restrict__ off_b2)
{
    if (blockIdx.x < 128) {
        if (threadIdx.x >= 256) return;
        const int id = blockIdx.x * 256 + threadIdx.x;   // 0..32767
        const int co = id >> 7, kp = id & 127;
        const float sc = g[co] * rsqrtf(v[co] + BN_EPS);
        const float w0 = w[co * 256 + 2 * kp] * sc;
        const float w1 = w[co * 256 + 2 * kp + 1] * sc;
        const uint32_t packed = packh(__float2half_rn(w0), __float2half_rn(w1));
        const int cb = co >> 4, mm = co & 15;
        const int kb = kp >> 3, kl = kp & 7;
        const int lane = (mm & 7) * 4 + (kl & 3);
        const int i = ((mm >> 3) & 1) | (((kl >> 2) & 1) << 1);
        g_wfragA[(((cb * 16) + kb) * 32 + lane) * 4 + i] = packed;
        if (kp == 0) g_bias[co] = bb[co] - m[co] * sc;
    } else {
        const int i = threadIdx.x;
        if (i < 288) {
            const int d = i / 144, rest = i % 144;
            float s = 0.f;
            for (int j = 0; j < 49; j++) s += off_w2[(d * 49 + j) * 144 + rest];
            g_wavg[i] = s * (1.f / 49.f);
        }
        if (i < 2) {
            float s = 0.f;
            for (int j = 0; j < 49; j++) s += off_b2[i * 49 + j];
            g_bavg[i] = s * (1.f / 49.f);
        }
    }
}

// ---------------------------------------------------------------------------
// Kernel 1: tensor-core GEMM, CTA = [256 co x 64 px], K=256 in 4 chunks of 64.
//   W via direct uint4 LDG of A fragments (L1/L2-hot); X double-buffered smem.
//   Epilogue: bias + SiLU -> fp16 store.  (R12-identical — the proven config)
// ---------------------------------------------------------------------------
__global__ void __launch_bounds__(256, 2) gemm_kernel(const float* __restrict__ X)
{
    extern __shared__ uint32_t sm[];
    const int tile = blockIdx.x, b = blockIdx.y;
    const int tileBase = tile * TILE_N;
    const int t = threadIdx.x, lane = t & 31, warp = t >> 5;   // warp = warpM 0..7
    const int q = lane >> 2, r = lane & 3;
    const float* Xb = X + (size_t)b * NC * NHW + tileBase;
    const int kq = t & 31, pg = t >> 5;

    const uint32_t smBase = (uint32_t)__cvta_generic_to_shared(sm);
    const uint32_t bOff = (uint32_t)((((lane & 16) ? 8 : 0) + (lane & 7)) * 20
                                     + ((lane & 8) ? 4 : 0));

    float acc[2][8][4];
    #pragma unroll
    for (int i = 0; i < 2; i++)
        #pragma unroll
        for (int j = 0; j < 8; j++)
            #pragma unroll
            for (int k = 0; k < 4; k++) acc[i][j][k] = 0.f;

    float4 xr0, xr1, xr2, xr3;

    auto ldgX = [&](int c) {
        const float* x0 = Xb + (size_t)(c * 64 + 2 * kq) * NHW + pg * 8;
        xr0 = *(const float4*)x0;         xr1 = *(const float4*)(x0 + 4);
        xr2 = *(const float4*)(x0 + NHW); xr3 = *(const float4*)(x0 + NHW + 4);
    };
    auto stsX = [&](int sx) {
        float e0[8] = {xr0.x, xr0.y, xr0.z, xr0.w, xr1.x, xr1.y, xr1.z, xr1.w};
        float e1[8] = {xr2.x, xr2.y, xr2.z, xr2.w, xr3.x, xr3.y, xr3.z, xr3.w};
        const int base = sx * 2560 + (kq >> 4) * 1280;
        const int kpc = kq & 15;
        #pragma unroll
        for (int j = 0; j < 8; j++) {
            sm[base + (pg * 8 + j) * 20 + kpc] =
                packh(__float2half_rn(e0[j]), __float2half_rn(e1[j]));
        }
    };

    const uint32_t wfBase = (uint32_t)(warp * 2 * 16 * 128 + lane * 4);

    // ---- prologue ----
    ldgX(0);
    stsX(0);
    ldgX(1);
    __syncthreads();

    for (int c = 0; c < 4; c++) {
        if (c < 3) stsX((c + 1) & 1);
        if (c < 2) ldgX(c + 2);

        const uint32_t xStgBase = smBase + (uint32_t)((c & 1) * 2560) * 4u;
        #pragma unroll
        for (int sub = 0; sub < 2; sub++) {
            const uint32_t xhS = xStgBase + (uint32_t)(sub * 1280) * 4u;
            #pragma unroll
            for (int ks = 0; ks < 2; ks++) {
                const int kb = c * 4 + sub * 2 + ks;
                uint4 A0 = *(const uint4*)&g_wfragA[wfBase + (0 * 16 + kb) * 128];
                uint4 A1 = *(const uint4*)&g_wfragA[wfBase + (1 * 16 + kb) * 128];
                #pragma unroll
                for (int np = 0; np < 4; np++) {
                    uint32_t B0[4];
                    ldsm4(B0, xhS + (bOff + np * 320 + ks * 8) * 4u);
                    #pragma unroll
                    for (int j = 0; j < 2; j++) {
                        mma16816h(acc[0][np * 2 + j], A0.x, A0.y, A0.z, A0.w,
                                  B0[2 * j], B0[2 * j + 1]);
                        mma16816h(acc[1][np * 2 + j], A1.x, A1.y, A1.z, A1.w,
                                  B0[2 * j], B0[2 * j + 1]);
                    }
                }
            }
        }
        __syncthreads();
    }

    // ---- epilogue: bias + SiLU + fp16 store ----
    #pragma unroll
    for (int mt = 0; mt < 2; mt++) {
        const int co0 = warp * 32 + mt * 16 + q;
        const int co1 = co0 + 8;
        const float tb0 = g_bias[co0], tb1 = g_bias[co1];
        __half* y0 = g_xalh + ((size_t)b * NC + co0) * NHW + tileBase;
        __half* y1 = g_xalh + ((size_t)b * NC + co1) * NHW + tileBase;
        #pragma unroll
        for (int nt = 0; nt < 8; nt++) {
            const int pix = nt * 8 + 2 * r;
            float v0 = acc[mt][nt][0] + tb0, v1 = acc[mt][nt][1] + tb0;
            float v2 = acc[mt][nt][2] + tb1, v3 = acc[mt][nt][3] + tb1;
            *(__half2*)&y0[pix] =
                __floats2half2_rn(v0 * sigmoidf_(v0), v1 * sigmoidf_(v1));
            *(__half2*)&y1[pix] =
                __floats2half2_rn(v2 * sigmoidf_(v2), v3 * sigmoidf_(v3));
        }
    }
}

// ---------------------------------------------------------------------------
// Kernel 2: per-(b,c) global sum/max + 4x4 local pool sums (fp16 input)
// ---------------------------------------------------------------------------
__global__ __launch_bounds__(160) void pool_kernel() {
    const int bc = blockIdx.x;
    const __half* plane = g_xalh + (size_t)bc * NHW;
    const int t = threadIdx.x, wb = t & 3, hr = t >> 2;

    float cell[4];
    float gmx = -1e30f;
    #pragma unroll
    for (int gy = 0; gy < 4; gy++) {
        const uint4* rp = (const uint4*)(plane + (gy * 40 + hr) * NW + wb * 40);
        float s = 0.f;
        #pragma unroll
        for (int i = 0; i < 5; i++) {           // 5 x 8 halves = 40
            uint4 v = rp[i];
            float2 f0 = h2f2(v.x), f1 = h2f2(v.y), f2 = h2f2(v.z), f3 = h2f2(v.w);
            s += (f0.x + f0.y) + (f1.x + f1.y) + (f2.x + f2.y) + (f3.x + f3.y);
            gmx = fmaxf(gmx, fmaxf(fmaxf(fmaxf(f0.x, f0.y), fmaxf(f1.x, f1.y)),
                                   fmaxf(fmaxf(f2.x, f2.y), fmaxf(f3.x, f3.y))));
        }
        cell[gy] = s;
    }
    float gs = (cell[0] + cell[1]) + (cell[2] + cell[3]);

    #pragma unroll
    for (int o = 4; o <= 16; o <<= 1)
        #pragma unroll
        for (int gy = 0; gy < 4; gy++)
            cell[gy] += __shfl_xor_sync(0xffffffffu, cell[gy], o);
    #pragma unroll
    for (int o = 1; o <= 16; o <<= 1) {
        gs += __shfl_xor_sync(0xffffffffu, gs, o);
        gmx = fmaxf(gmx, __shfl_xor_sync(0xffffffffu, gmx, o));
    }

    __shared__ float sC[5][4][4], sS[5], sM[5];
    const int w = t >> 5, lanei = t & 31;
    if (lanei < 4) {
        #pragma unroll
        for (int gy = 0; gy < 4; gy++) sC[w][gy][lanei] = cell[gy];
    }
    if (lanei == 0) { sS[w] = gs; sM[w] = gmx; }
    __syncthreads();
    if (t < 16) {
        float v = 0.f;
        #pragma unroll
        for (int w2 = 0; w2 < 5; w2++) v += sC[w2][t >> 2][t & 3];
        g_lsum[bc * 16 + t] = v;
    }
    if (t == 0) {
        float S = 0.f, M = -1e30f;
        #pragma unroll
        for (int w2 = 0; w2 < 5; w2++) { S += sS[w2]; M = fmaxf(M, sM[w2]); }
        g_gsum[bc] = S;
        g_gmax[bc] = M;
    }
}

// ---------------------------------------------------------------------------
// Kernel 4: channel attention -> g_ca
// ---------------------------------------------------------------------------
__global__ __launch_bounds__(256) void ca_kernel(
    const float* __restrict__ mlp_w1, const float* __restrict__ mlp_w2,
    const float* __restrict__ loc_w1, const float* __restrict__ loc_w2,
    const float* __restrict__ fusion_w)
{
    const int b = blockIdx.x, tid = threadIdx.x;
    __shared__ float avg[256], mxv[256];
    __shared__ float h1[32], hpart[32][8], hcell[16][16], hbar[16];

    avg[tid] = g_gsum[b * NC + tid] * (1.f / (float)NHW);
    mxv[tid] = g_gmax[b * NC + tid];
    __syncthreads();

    {
        const int m = tid >> 3, part = tid & 7;
        const int mm = m & 15;
        const float* src = (m < 16) ? avg : mxv;
        float a = 0.f;
        #pragma unroll 8
        for (int c = part * 32; c < part * 32 + 32; c++)
            a += mlp_w1[mm * NC + c] * src[c];
        hpart[m][part] = a;
    }
    {
        const int cell = tid >> 4, m2 = tid & 15;
        float a = 0.f;
        #pragma unroll 8
        for (int c = 0; c < NC; c++)
            a += loc_w1[m2 * NC + c] * g_lsum[(b * NC + c) * 16 + cell];
        hcell[cell][m2] = fmaxf(a * (1.f / 1600.f), 0.f);
    }
    __syncthreads();
    if (tid < 32) {
        float a = 0.f;
        #pragma unroll
        for (int p = 0; p < 8; p++) a += hpart[tid][p];
        h1[tid] = fmaxf(a, 0.f);
    }
    if (tid >= 32 && tid < 48) {
        float s = 0.f;
        #pragma unroll
        for (int cell = 0; cell < 16; cell++) s += hcell[cell][tid - 32];
        hbar[tid - 32] = s * (1.f / 16.f);
    }
    __syncthreads();

    float ga = 0.f, la = 0.f;
    #pragma unroll
    for (int m = 0; m < 16; m++) {
        ga += mlp_w2[tid * 16 + m] * (h1[m] + h1[16 + m]);
        la += loc_w2[tid * 16 + m] * hbar[m];
    }
    const float alpha = sigmoidf_(fusion_w[0]);
    g_ca[b * NC + tid] = sigmoidf_(alpha * ga + (1.f - alpha) * la);
}

// ---------------------------------------------------------------------------
// Kernel 5: sf = [mean_c(ca*x), max_c(ca*x)]  (fp16 input, 4 px / thread)
// ---------------------------------------------------------------------------
__global__ __launch_bounds__(256) void sf_kernel() {
    const int b = blockIdx.y;
    const int p4 = blockIdx.x * 256 + threadIdx.x;       // 0..6399
    const __half* xb = g_xalh + (size_t)b * NC * NHW;
    const float* cab = g_ca + b * NC;
    float4 s = make_float4(0.f, 0.f, 0.f, 0.f);
    float4 mx = make_float4(-1e30f, -1e30f, -1e30f, -1e30f);
    #pragma unroll 4
    for (int c = 0; c < NC; c++) {
        const float cc = cab[c];
        uint2 u = *(const uint2*)(xb + (size_t)c * NHW + p4 * 4);
        float2 f0 = h2f2(u.x), f1 = h2f2(u.y);
        float v0 = cc * f0.x, v1 = cc * f0.y, v2 = cc * f1.x, v3 = cc * f1.y;
        s.x += v0; s.y += v1; s.z += v2; s.w += v3;
        mx.x = fmaxf(mx.x, v0); mx.y = fmaxf(mx.y, v1);
        mx.z = fmaxf(mx.z, v2); mx.w = fmaxf(mx.w, v3);
    }
    const float inv = 1.f / (float)NC;
    s.x *= inv; s.y *= inv; s.z *= inv; s.w *= inv;
    ((float4*)(g_sf + (size_t)b * 2 * NHW))[p4] = s;
    ((float4*)(g_sf + (size_t)b * 2 * NHW + NHW))[p4] = mx;
}

// ---------------------------------------------------------------------------
// Kernel 6: offset conv1: 3x3, 2->16 + BN + ReLU
// ---------------------------------------------------------------------------
__global__ __launch_bounds__(256) void off1_kernel(
    const float* __restrict__ w1, const float* __restrict__ gg,
    const float* __restrict__ bt, const float* __restrict__ mm,
    const float* __restrict__ vv)
{
    const int p = blockIdx.x * blockDim.x + threadIdx.x;
    const int co = blockIdx.y, b = blockIdx.z;
    const int h = p / NW, w = p % NW;
    const float* sfb = g_sf + (size_t)b * 2 * NHW;
    float acc = 0.f;
    #pragma unroll
    for (int ci = 0; ci < 2; ci++) {
        #pragma unroll
        for (int ky = 0; ky < 3; ky++) {
            const int hy = h + ky - 1;
            if (hy < 0 || hy >= NH) continue;
            #pragma unroll
            for (int kx = 0; kx < 3; kx++) {
                const int wx = w + kx - 1;
                if (wx < 0 || wx >= NW) continue;
                acc += w1[((co * 2 + ci) * 3 + ky) * 3 + kx] *
                       sfb[ci * NHW + hy * NW + wx];
            }
        }
    }
    const float sc = gg[co] * rsqrtf(vv[co] + BN_EPS);
    const float tb = bt[co] - mm[co] * sc;
    g_o1[((size_t)b * 16 + co) * NHW + p] = fmaxf(acc * sc + tb, 0.f);
}

// ---------------------------------------------------------------------------
// Kernel 7: averaged offset conv2 + tanh*0.5 + grid + bilinear sample
// ---------------------------------------------------------------------------
__global__ __launch_bounds__(256) void off2_sample_kernel() {
    const int b = blockIdx.y;
    const int p = blockIdx.x * blockDim.x + threadIdx.x;
    const int h = p / NW, w = p % NW;
    const float* o1b = g_o1 + (size_t)b * 16 * NHW;

    float off[2];
    #pragma unroll
    for (int d = 0; d < 2; d++) {
        float acc = g_bavg[d];
        for (int ci = 0; ci < 16; ci++) {
            #pragma unroll
            for (int ky = 0; ky < 3; ky++) {
                const int hy = h + ky - 1;
                if (hy < 0 || hy >= NH) continue;
                #pragma unroll
                for (int kx = 0; kx < 3; kx++) {
                    const int wx = w + kx - 1;
                    if (wx < 0 || wx >= NW) continue;
                    acc += g_wavg[(d * 16 + ci) * 9 + ky * 3 + kx] *
                           o1b[(size_t)ci * NHW + hy * NW + wx];
                }
            }
        }
        off[d] = tanhf(acc) * 0.5f;
    }

    const float bx = -1.f + 2.f * (float)w / 159.f;
    const float by = -1.f + 2.f * (float)h / 159.f;
    const float gx = fminf(fmaxf(bx + off[0], -1.f), 1.f);
    const float gy = fminf(fmaxf(by + off[1], -1.f), 1.f);

    const float fx = (gx + 1.f) * ((float)NW * 0.5f) - 0.5f;
    const float fy = (gy + 1.f) * ((float)NH * 0.5f) - 0.5f;
    const float x0f = floorf(fx), y0f = floorf(fy);
    const int x0 = (int)x0f, y0 = (int)y0f;
    const float wx = fx - x0f, wy = fy - y0f;

    const float* sfb = g_sf + (size_t)b * 2 * NHW;
    float out0 = 0.f, out1 = 0.f;
    #pragma unroll
    for (int dy = 0; dy < 2; dy++) {
        const int yy = y0 + dy;
        if (yy < 0 || yy >= NH) continue;
        const float wgy = dy ? wy : (1.f - wy);
        #pragma unroll
        for (int dx = 0; dx < 2; dx++) {
            const int xx = x0 + dx;
            if (xx < 0 || xx >= NW) continue;
            const float wt = wgy * (dx ? wx : (1.f - wx));
            out0 += wt * sfb[yy * NW + xx];
            out1 += wt * sfb[NHW + yy * NW + xx];
        }
    }
    g_sampled[(size_t)b * 2 * NHW + p] = out0;
    g_sampled[(size_t)b * 2 * NHW + NHW + p] = out1;
}

// ---------------------------------------------------------------------------
// Kernel 8: 7x7 conv (2->1) over sampled + sigmoid -> g_sa
// ---------------------------------------------------------------------------
__global__ __launch_bounds__(256) void sa_kernel(const float* __restrict__ attn_w) {
    const int b = blockIdx.y;
    const int p = blockIdx.x * blockDim.x + threadIdx.x;
    const int h = p / NW, w = p % NW;
    const float* sm = g_sampled + (size_t)b * 2 * NHW;
    float acc = 0.f;
    #pragma unroll
    for (int ci = 0; ci < 2; ci++) {
        #pragma unroll
        for (int ky = 0; ky < 7; ky++) {
            const int hy = h + ky - 3;
            if (hy < 0 || hy >= NH) continue;
            #pragma unroll
            for (int kx = 0; kx < 7; kx++) {
                const int wx = w + kx - 3;
                if (wx < 0 || wx >= NW) continue;
                acc += attn_w[(ci * 7 + ky) * 7 + kx] *
                       sm[ci * NHW + hy * NW + wx];
            }
        }
    }
    g_sa[b * NHW + p] = sigmoidf_(acc);
}

// ---------------------------------------------------------------------------
// Kernel 9: out = sa * ca * x_aligned  (fp16 xal, 8 elems / thread)
// ---------------------------------------------------------------------------
__global__ __launch_bounds__(256) void final_kernel(float* __restrict__ out) {
    const unsigned idx8 = blockIdx.x * blockDim.x + threadIdx.x;
    const unsigned total8 = (unsigned)NB * NC * NHW / 8;
    if (idx8 >= total8) return;
    const unsigned e = idx8 * 8;
    const unsigned p = e % NHW;
    const unsigned c = (e / NHW) % NC;
    const unsigned b = e / (NHW * NC);
    uint4 u = *(const uint4*)(g_xalh + e);
    float2 f0 = h2f2(u.x), f1 = h2f2(u.y), f2 = h2f2(u.z), f3 = h2f2(u.w);
    const float4 sa0 = *reinterpret_cast<const float4*>(&g_sa[b * NHW + p]);
    const float4 sa1 = *reinterpret_cast<const float4*>(&g_sa[b * NHW + p + 4]);
    const float cc = g_ca[b * NC + c];
    float4 r0, r1;
    r0.x = f0.x * sa0.x * cc;  r0.y = f0.y * sa0.y * cc;
    r0.z = f1.x * sa0.z * cc;  r0.w = f1.y * sa0.w * cc;
    r1.x = f2.x * sa1.x * cc;  r1.y = f2.y * sa1.y * cc;
    r1.z = f3.x * sa1.z * cc;  r1.w = f3.y * sa1.w * cc;
    *reinterpret_cast<float4*>(&out[e]) = r0;
    *reinterpret_cast<float4*>(&out[e + 4]) = r1;
}

// ---------------------------------------------------------------------------
extern "C" void kernel_launch(void* const* d_in, const int* in_sizes, int n_in,
                              void* d_out, int out_size) {
    const float* x       = (const float*)d_in[0];
    const float* align_w = (const float*)d_in[1];
    const float* align_g = (const float*)d_in[2];
    const float* align_b = (const float*)d_in[3];
    const float* align_m = (const float*)d_in[4];
    const float* align_v = (const float*)d_in[5];
    const float* mlp_w1  = (const float*)d_in[6];
    const float* mlp_w2  = (const float*)d_in[7];
    const float* loc_w1  = (const float*)d_in[8];
    const float* loc_w2  = (const float*)d_in[9];
    const float* fusion  = (const float*)d_in[10];
    const float* off_w1  = (const float*)d_in[11];
    const float* off_g   = (const float*)d_in[12];
    const float* off_bt  = (const float*)d_in[13];
    const float* off_m   = (const float*)d_in[14];
    const float* off_v   = (const float*)d_in[15];
    const float* off_w2  = (const float*)d_in[16];
    const float* off_b2  = (const float*)d_in[17];
    const float* attn_w  = (const float*)d_in[18];
    float* out = (float*)d_out;

    wprep_kernel<<<129, 288>>>(align_w, align_g, align_b, align_m, align_v,
                               off_w2, off_b2);

    dim3 gGemm(NTILES, NB);
    gemm_kernel<<<gGemm, 256, DSMEM_U32 * 4>>>(x);

    pool_kernel<<<NB * NC, 160>>>();
    ca_kernel<<<NB, 256>>>(mlp_w1, mlp_w2, loc_w1, loc_w2, fusion);

    dim3 gPix4(NHW / 4 / 256, NB);
    sf_kernel<<<gPix4, 256>>>();

    dim3 gPix(NHW / 256, NB);
    dim3 gOff1(NHW / 256, 16, NB);
    off1_kernel<<<gOff1, 256>>>(off_w1, off_g, off_bt, off_m, off_v);
    off2_sample_kernel<<<gPix, 256>>>();
    sa_kernel<<<gPix, 256>>>(attn_w);

    const unsigned total8 = (unsigned)NB * NC * NHW / 8;
    final_kernel<<<(total8 + 255) / 256, 256>>>(out);
}

// round 17
// speedup vs baseline: 1.3408x; 1.0401x over previous
#include <cuda_runtime.h>
#include <cuda_fp16.h>
#include <cstdint>

static constexpr int NB = 8;
static constexpr int NC = 256;
static constexpr int NH = 160;
static constexpr int NW = 160;
static constexpr int NHW = NH * NW;           // 25600
static constexpr int TILE_N = 64;
static constexpr int NTILES = NHW / TILE_N;   // 400
static constexpr float BN_EPS = 1e-5f;

// dynamic smem (u32 units): X double buffer, 2 stages x 2560 (2 subs of 1280)
static constexpr int DSMEM_U32 = 5120;        // 20 KB

// ---------------- scratch (static device globals) --------------------------
__device__ __half g_xalh[(size_t)NB * NC * NHW];   // fp16 aligned activations
__device__ uint32_t g_wfragA[256 * 128];  // W in mma-A-fragment layout (128 KB)
__device__ float g_bias[NC];
__device__ float g_gsum[NB * NC];
__device__ float g_gmax[NB * NC];
__device__ float g_lsum[NB * NC * 16];
__device__ float g_ca[NB * NC];
__device__ float g_sf[NB * 2 * NHW];
__device__ float g_o1[NB * 16 * NHW];
__device__ float g_sampled[NB * 2 * NHW];
__device__ float g_sa[NB * NHW];
__device__ float g_wavg[2 * 16 * 9];
__device__ float g_bavg[2];

__device__ __forceinline__ float sigmoidf_(float x) {
    return 1.f / (1.f + __expf(-x));
}
__device__ __forceinline__ uint32_t packh(__half a, __half b) {
    __half2 t = __halves2half2(a, b);     // low = a
    return *reinterpret_cast<uint32_t*>(&t);
}
__device__ __forceinline__ float2 h2f2(uint32_t u) {
    return __half22float2(*reinterpret_cast<__half2*>(&u));
}
__device__ __forceinline__ void mma16816h(float* c, uint32_t a0, uint32_t a1,
                                          uint32_t a2, uint32_t a3,
                                          uint32_t b0, uint32_t b1) {
    asm volatile(
        "mma.sync.aligned.m16n8k16.row.col.f32.f16.f16.f32 "
        "{%0,%1,%2,%3}, {%4,%5,%6,%7}, {%8,%9}, {%0,%1,%2,%3};"
        : "+f"(c[0]), "+f"(c[1]), "+f"(c[2]), "+f"(c[3])
        : "r"(a0), "r"(a1), "r"(a2), "r"(a3), "r"(b0), "r"(b1));
}
__device__ __forceinline__ void ldsm4(uint32_t* d, uint32_t addr) {
    asm volatile(
        "ldmatrix.sync.aligned.m8n8.x4.shared.b16 {%0,%1,%2,%3}, [%4];"
        : "=r"(d[0]), "=r"(d[1]), "=r"(d[2]), "=r"(d[3]) : "r"(addr));
}

// ---------------------------------------------------------------------------
// Kernel 0: W pack (A-fragment layout) + averaged offset-conv2 weights
// ---------------------------------------------------------------------------
__global__ __launch_bounds__(288) void wprep_kernel(
    const float* __restrict__ w, const float* __restrict__ g,
    const float* __restrict__ bb, const float* __restrict__ m,
    const float* __restrict__ v,
    const float* __restrict__ off_w2, const float* __restrict__ off_b2)
{
    if (blockIdx.x < 128) {
        if (threadIdx.x >= 256) return;
        const int id = blockIdx.x * 256 + threadIdx.x;   // 0..32767
        const int co = id >> 7, kp = id & 127;
        const float sc = g[co] * rsqrtf(v[co] + BN_EPS);
        const float w0 = w[co * 256 + 2 * kp] * sc;
        const float w1 = w[co * 256 + 2 * kp + 1] * sc;
        const uint32_t packed = packh(__float2half_rn(w0), __float2half_rn(w1));
        const int cb = co >> 4, mm = co & 15;
        const int kb = kp >> 3, kl = kp & 7;
        const int lane = (mm & 7) * 4 + (kl & 3);
        const int i = ((mm >> 3) & 1) | (((kl >> 2) & 1) << 1);
        g_wfragA[(((cb * 16) + kb) * 32 + lane) * 4 + i] = packed;
        if (kp == 0) g_bias[co] = bb[co] - m[co] * sc;
    } else {
        const int i = threadIdx.x;
        if (i < 288) {
            const int d = i / 144, rest = i % 144;
            float s = 0.f;
            for (int j = 0; j < 49; j++) s += off_w2[(d * 49 + j) * 144 + rest];
            g_wavg[i] = s * (1.f / 49.f);
        }
        if (i < 2) {
            float s = 0.f;
            for (int j = 0; j < 49; j++) s += off_b2[i * 49 + j];
            g_bavg[i] = s * (1.f / 49.f);
        }
    }
}

// ---------------------------------------------------------------------------
// Kernel 1: tensor-core GEMM (R12-proven config, untouched)
// ---------------------------------------------------------------------------
__global__ void __launch_bounds__(256, 2) gemm_kernel(const float* __restrict__ X)
{
    extern __shared__ uint32_t sm[];
    const int tile = blockIdx.x, b = blockIdx.y;
    const int tileBase = tile * TILE_N;
    const int t = threadIdx.x, lane = t & 31, warp = t >> 5;
    const int q = lane >> 2, r = lane & 3;
    const float* Xb = X + (size_t)b * NC * NHW + tileBase;
    const int kq = t & 31, pg = t >> 5;

    const uint32_t smBase = (uint32_t)__cvta_generic_to_shared(sm);
    const uint32_t bOff = (uint32_t)((((lane & 16) ? 8 : 0) + (lane & 7)) * 20
                                     + ((lane & 8) ? 4 : 0));

    float acc[2][8][4];
    #pragma unroll
    for (int i = 0; i < 2; i++)
        #pragma unroll
        for (int j = 0; j < 8; j++)
            #pragma unroll
            for (int k = 0; k < 4; k++) acc[i][j][k] = 0.f;

    float4 xr0, xr1, xr2, xr3;

    auto ldgX = [&](int c) {
        const float* x0 = Xb + (size_t)(c * 64 + 2 * kq) * NHW + pg * 8;
        xr0 = *(const float4*)x0;         xr1 = *(const float4*)(x0 + 4);
        xr2 = *(const float4*)(x0 + NHW); xr3 = *(const float4*)(x0 + NHW + 4);
    };
    auto stsX = [&](int sx) {
        float e0[8] = {xr0.x, xr0.y, xr0.z, xr0.w, xr1.x, xr1.y, xr1.z, xr1.w};
        float e1[8] = {xr2.x, xr2.y, xr2.z, xr2.w, xr3.x, xr3.y, xr3.z, xr3.w};
        const int base = sx * 2560 + (kq >> 4) * 1280;
        const int kpc = kq & 15;
        #pragma unroll
        for (int j = 0; j < 8; j++) {
            sm[base + (pg * 8 + j) * 20 + kpc] =
                packh(__float2half_rn(e0[j]), __float2half_rn(e1[j]));
        }
    };

    const uint32_t wfBase = (uint32_t)(warp * 2 * 16 * 128 + lane * 4);

    ldgX(0);
    stsX(0);
    ldgX(1);
    __syncthreads();

    for (int c = 0; c < 4; c++) {
        if (c < 3) stsX((c + 1) & 1);
        if (c < 2) ldgX(c + 2);

        const uint32_t xStgBase = smBase + (uint32_t)((c & 1) * 2560) * 4u;
        #pragma unroll
        for (int sub = 0; sub < 2; sub++) {
            const uint32_t xhS = xStgBase + (uint32_t)(sub * 1280) * 4u;
            #pragma unroll
            for (int ks = 0; ks < 2; ks++) {
                const int kb = c * 4 + sub * 2 + ks;
                uint4 A0 = *(const uint4*)&g_wfragA[wfBase + (0 * 16 + kb) * 128];
                uint4 A1 = *(const uint4*)&g_wfragA[wfBase + (1 * 16 + kb) * 128];
                #pragma unroll
                for (int np = 0; np < 4; np++) {
                    uint32_t B0[4];
                    ldsm4(B0, xhS + (bOff + np * 320 + ks * 8) * 4u);
                    #pragma unroll
                    for (int j = 0; j < 2; j++) {
                        mma16816h(acc[0][np * 2 + j], A0.x, A0.y, A0.z, A0.w,
                                  B0[2 * j], B0[2 * j + 1]);
                        mma16816h(acc[1][np * 2 + j], A1.x, A1.y, A1.z, A1.w,
                                  B0[2 * j], B0[2 * j + 1]);
                    }
                }
            }
        }
        __syncthreads();
    }

    #pragma unroll
    for (int mt = 0; mt < 2; mt++) {
        const int co0 = warp * 32 + mt * 16 + q;
        const int co1 = co0 + 8;
        const float tb0 = g_bias[co0], tb1 = g_bias[co1];
        __half* y0 = g_xalh + ((size_t)b * NC + co0) * NHW + tileBase;
        __half* y1 = g_xalh + ((size_t)b * NC + co1) * NHW + tileBase;
        #pragma unroll
        for (int nt = 0; nt < 8; nt++) {
            const int pix = nt * 8 + 2 * r;
            float v0 = acc[mt][nt][0] + tb0, v1 = acc[mt][nt][1] + tb0;
            float v2 = acc[mt][nt][2] + tb1, v3 = acc[mt][nt][3] + tb1;
            *(__half2*)&y0[pix] =
                __floats2half2_rn(v0 * sigmoidf_(v0), v1 * sigmoidf_(v1));
            *(__half2*)&y1[pix] =
                __floats2half2_rn(v2 * sigmoidf_(v2), v3 * sigmoidf_(v3));
        }
    }
}

// ---------------------------------------------------------------------------
// Kernel 2: per-(b,c) global sum/max + 4x4 local pool sums (fp16 input)
// ---------------------------------------------------------------------------
__global__ __launch_bounds__(160) void pool_kernel() {
    const int bc = blockIdx.x;
    const __half* plane = g_xalh + (size_t)bc * NHW;
    const int t = threadIdx.x, wb = t & 3, hr = t >> 2;

    float cell[4];
    float gmx = -1e30f;
    #pragma unroll
    for (int gy = 0; gy < 4; gy++) {
        const uint4* rp = (const uint4*)(plane + (gy * 40 + hr) * NW + wb * 40);
        float s = 0.f;
        #pragma unroll
        for (int i = 0; i < 5; i++) {
            uint4 v = rp[i];
            float2 f0 = h2f2(v.x), f1 = h2f2(v.y), f2 = h2f2(v.z), f3 = h2f2(v.w);
            s += (f0.x + f0.y) + (f1.x + f1.y) + (f2.x + f2.y) + (f3.x + f3.y);
            gmx = fmaxf(gmx, fmaxf(fmaxf(fmaxf(f0.x, f0.y), fmaxf(f1.x, f1.y)),
                                   fmaxf(fmaxf(f2.x, f2.y), fmaxf(f3.x, f3.y))));
        }
        cell[gy] = s;
    }
    float gs = (cell[0] + cell[1]) + (cell[2] + cell[3]);

    #pragma unroll
    for (int o = 4; o <= 16; o <<= 1)
        #pragma unroll
        for (int gy = 0; gy < 4; gy++)
            cell[gy] += __shfl_xor_sync(0xffffffffu, cell[gy], o);
    #pragma unroll
    for (int o = 1; o <= 16; o <<= 1) {
        gs += __shfl_xor_sync(0xffffffffu, gs, o);
        gmx = fmaxf(gmx, __shfl_xor_sync(0xffffffffu, gmx, o));
    }

    __shared__ float sC[5][4][4], sS[5], sM[5];
    const int w = t >> 5, lanei = t & 31;
    if (lanei < 4) {
        #pragma unroll
        for (int gy = 0; gy < 4; gy++) sC[w][gy][lanei] = cell[gy];
    }
    if (lanei == 0) { sS[w] = gs; sM[w] = gmx; }
    __syncthreads();
    if (t < 16) {
        float v = 0.f;
        #pragma unroll
        for (int w2 = 0; w2 < 5; w2++) v += sC[w2][t >> 2][t & 3];
        g_lsum[bc * 16 + t] = v;
    }
    if (t == 0) {
        float S = 0.f, M = -1e30f;
        #pragma unroll
        for (int w2 = 0; w2 < 5; w2++) { S += sS[w2]; M = fmaxf(M, sM[w2]); }
        g_gsum[bc] = S;
        g_gmax[bc] = M;
    }
}

// ---------------------------------------------------------------------------
// Kernel 4: channel attention -> g_ca  (smem-staged, coalesced loads)
// ---------------------------------------------------------------------------
__global__ __launch_bounds__(256) void ca_kernel(
    const float* __restrict__ mlp_w1, const float* __restrict__ mlp_w2,
    const float* __restrict__ loc_w1, const float* __restrict__ loc_w2,
    const float* __restrict__ fusion_w)
{
    const int b = blockIdx.x, tid = threadIdx.x;
    __shared__ float avg[256], mxv[256];
    __shared__ float ls[4096];          // g_lsum[b], linear [c*16+cell]
    __shared__ float w1s[16 * 257];     // mlp_w1 padded rows
    __shared__ float lw1[16 * 257];     // loc_w1 padded rows
    __shared__ float h1[32], hpart[32][8], hcell[16][16], hbar[16];

    avg[tid] = g_gsum[b * NC + tid] * (1.f / (float)NHW);
    mxv[tid] = g_gmax[b * NC + tid];
    #pragma unroll
    for (int i = 0; i < 16; i++) {
        const int idx = i * 256 + tid;
        ls[idx] = g_lsum[b * 4096 + idx];
        w1s[(idx >> 8) * 257 + (idx & 255)] = mlp_w1[idx];
        lw1[(idx >> 8) * 257 + (idx & 255)] = loc_w1[idx];
    }
    __syncthreads();

    {   // h1 partial dots: 8 threads per hidden unit
        const int m = tid >> 3, part = tid & 7;
        const int mm = m & 15;
        const float* src = (m < 16) ? avg : mxv;
        float a = 0.f;
        #pragma unroll 8
        for (int c = part * 32; c < part * 32 + 32; c++)
            a += w1s[mm * 257 + c] * src[c];
        hpart[m][part] = a;
    }
    {   // hcell: one thread per (cell, m2), all smem
        const int cell = tid >> 4, m2 = tid & 15;
        float a = 0.f;
        #pragma unroll 8
        for (int c = 0; c < NC; c++)
            a += lw1[m2 * 257 + c] * ls[c * 16 + cell];
        hcell[cell][m2] = fmaxf(a * (1.f / 1600.f), 0.f);
    }
    __syncthreads();
    if (tid < 32) {
        float a = 0.f;
        #pragma unroll
        for (int p = 0; p < 8; p++) a += hpart[tid][p];
        h1[tid] = fmaxf(a, 0.f);
    }
    if (tid >= 32 && tid < 48) {
        float s = 0.f;
        #pragma unroll
        for (int cell = 0; cell < 16; cell++) s += hcell[cell][tid - 32];
        hbar[tid - 32] = s * (1.f / 16.f);
    }
    __syncthreads();

    float ga = 0.f, la = 0.f;
    #pragma unroll
    for (int m = 0; m < 16; m++) {
        ga += mlp_w2[tid * 16 + m] * (h1[m] + h1[16 + m]);
        la += loc_w2[tid * 16 + m] * hbar[m];
    }
    const float alpha = sigmoidf_(fusion_w[0]);
    g_ca[b * NC + tid] = sigmoidf_(alpha * ga + (1.f - alpha) * la);
}

// ---------------------------------------------------------------------------
// Kernel 5: sf = [mean_c(ca*x), max_c(ca*x)]  (fp16 input, 8 px / thread)
// ---------------------------------------------------------------------------
__global__ __launch_bounds__(128) void sf_kernel() {
    const int b = blockIdx.y;
    const int p8 = blockIdx.x * 128 + threadIdx.x;       // 0..3199
    const __half* xb = g_xalh + (size_t)b * NC * NHW;
    const float* cab = g_ca + b * NC;
    float s[8], mx[8];
    #pragma unroll
    for (int i = 0; i < 8; i++) { s[i] = 0.f; mx[i] = -1e30f; }
    #pragma unroll 4
    for (int c = 0; c < NC; c++) {
        const float cc = cab[c];
        uint4 u = *(const uint4*)(xb + (size_t)c * NHW + p8 * 8);
        float2 f0 = h2f2(u.x), f1 = h2f2(u.y), f2 = h2f2(u.z), f3 = h2f2(u.w);
        float v[8] = {cc * f0.x, cc * f0.y, cc * f1.x, cc * f1.y,
                      cc * f2.x, cc * f2.y, cc * f3.x, cc * f3.y};
        #pragma unroll
        for (int i = 0; i < 8; i++) {
            s[i] += v[i];
            mx[i] = fmaxf(mx[i], v[i]);
        }
    }
    const float inv = 1.f / (float)NC;
    float4 s0 = make_float4(s[0] * inv, s[1] * inv, s[2] * inv, s[3] * inv);
    float4 s1 = make_float4(s[4] * inv, s[5] * inv, s[6] * inv, s[7] * inv);
    float* dm = g_sf + (size_t)b * 2 * NHW + p8 * 8;
    *(float4*)dm = s0;
    *(float4*)(dm + 4) = s1;
    float* dx = dm + NHW;
    *(float4*)dx = make_float4(mx[0], mx[1], mx[2], mx[3]);
    *(float4*)(dx + 4) = make_float4(mx[4], mx[5], mx[6], mx[7]);
}

// ---------------------------------------------------------------------------
// Kernel 6: offset conv1: 3x3, 2->16 + BN + ReLU
// ---------------------------------------------------------------------------
__global__ __launch_bounds__(256) void off1_kernel(
    const float* __restrict__ w1, const float* __restrict__ gg,
    const float* __restrict__ bt, const float* __restrict__ mm,
    const float* __restrict__ vv)
{
    const int p = blockIdx.x * blockDim.x + threadIdx.x;
    const int co = blockIdx.y, b = blockIdx.z;
    const int h = p / NW, w = p % NW;
    const float* sfb = g_sf + (size_t)b * 2 * NHW;
    float acc = 0.f;
    #pragma unroll
    for (int ci = 0; ci < 2; ci++) {
        #pragma unroll
        for (int ky = 0; ky < 3; ky++) {
            const int hy = h + ky - 1;
            if (hy < 0 || hy >= NH) continue;
            #pragma unroll
            for (int kx = 0; kx < 3; kx++) {
                const int wx = w + kx - 1;
                if (wx < 0 || wx >= NW) continue;
                acc += w1[((co * 2 + ci) * 3 + ky) * 3 + kx] *
                       sfb[ci * NHW + hy * NW + wx];
            }
        }
    }
    const float sc = gg[co] * rsqrtf(vv[co] + BN_EPS);
    const float tb = bt[co] - mm[co] * sc;
    g_o1[((size_t)b * 16 + co) * NHW + p] = fmaxf(acc * sc + tb, 0.f);
}

// ---------------------------------------------------------------------------
// Kernel 7: averaged offset conv2 + tanh*0.5 + grid + bilinear sample
// ---------------------------------------------------------------------------
__global__ __launch_bounds__(256) void off2_sample_kernel() {
    const int b = blockIdx.y;
    const int p = blockIdx.x * blockDim.x + threadIdx.x;
    const int h = p / NW, w = p % NW;
    const float* o1b = g_o1 + (size_t)b * 16 * NHW;

    float off[2];
    #pragma unroll
    for (int d = 0; d < 2; d++) {
        float acc = g_bavg[d];
        for (int ci = 0; ci < 16; ci++) {
            #pragma unroll
            for (int ky = 0; ky < 3; ky++) {
                const int hy = h + ky - 1;
                if (hy < 0 || hy >= NH) continue;
                #pragma unroll
                for (int kx = 0; kx < 3; kx++) {
                    const int wx = w + kx - 1;
                    if (wx < 0 || wx >= NW) continue;
                    acc += g_wavg[(d * 16 + ci) * 9 + ky * 3 + kx] *
                           o1b[(size_t)ci * NHW + hy * NW + wx];
                }
            }
        }
        off[d] = tanhf(acc) * 0.5f;
    }

    const float bx = -1.f + 2.f * (float)w / 159.f;
    const float by = -1.f + 2.f * (float)h / 159.f;
    const float gx = fminf(fmaxf(bx + off[0], -1.f), 1.f);
    const float gy = fminf(fmaxf(by + off[1], -1.f), 1.f);

    const float fx = (gx + 1.f) * ((float)NW * 0.5f) - 0.5f;
    const float fy = (gy + 1.f) * ((float)NH * 0.5f) - 0.5f;
    const float x0f = floorf(fx), y0f = floorf(fy);
    const int x0 = (int)x0f, y0 = (int)y0f;
    const float wx = fx - x0f, wy = fy - y0f;

    const float* sfb = g_sf + (size_t)b * 2 * NHW;
    float out0 = 0.f, out1 = 0.f;
    #pragma unroll
    for (int dy = 0; dy < 2; dy++) {
        const int yy = y0 + dy;
        if (yy < 0 || yy >= NH) continue;
        const float wgy = dy ? wy : (1.f - wy);
        #pragma unroll
        for (int dx = 0; dx < 2; dx++) {
            const int xx = x0 + dx;
            if (xx < 0 || xx >= NW) continue;
            const float wt = wgy * (dx ? wx : (1.f - wx));
            out0 += wt * sfb[yy * NW + xx];
            out1 += wt * sfb[NHW + yy * NW + xx];
        }
    }
    g_sampled[(size_t)b * 2 * NHW + p] = out0;
    g_sampled[(size_t)b * 2 * NHW + NHW + p] = out1;
}

// ---------------------------------------------------------------------------
// Kernel 8: 7x7 conv (2->1) over sampled + sigmoid -> g_sa
// ---------------------------------------------------------------------------
__global__ __launch_bounds__(256) void sa_kernel(const float* __restrict__ attn_w) {
    const int b = blockIdx.y;
    const int p = blockIdx.x * blockDim.x + threadIdx.x;
    const int h = p / NW, w = p % NW;
    const float* sm = g_sampled + (size_t)b * 2 * NHW;
    float acc = 0.f;
    #pragma unroll
    for (int ci = 0; ci < 2; ci++) {
        #pragma unroll
        for (int ky = 0; ky < 7; ky++) {
            const int hy = h + ky - 3;
            if (hy < 0 || hy >= NH) continue;
            #pragma unroll
            for (int kx = 0; kx < 7; kx++) {
                const int wx = w + kx - 3;
                if (wx < 0 || wx >= NW) continue;
                acc += attn_w[(ci * 7 + ky) * 7 + kx] *
                       sm[ci * NHW + hy * NW + wx];
            }
        }
    }
    g_sa[b * NHW + p] = sigmoidf_(acc);
}

// ---------------------------------------------------------------------------
// Kernel 9: out = sa * ca * x_aligned  (fp16 xal, 8 elems / thread)
// ---------------------------------------------------------------------------
__global__ __launch_bounds__(256) void final_kernel(float* __restrict__ out) {
    const unsigned idx8 = blockIdx.x * blockDim.x + threadIdx.x;
    const unsigned total8 = (unsigned)NB * NC * NHW / 8;
    if (idx8 >= total8) return;
    const unsigned e = idx8 * 8;
    const unsigned p = e % NHW;
    const unsigned c = (e / NHW) % NC;
    const unsigned b = e / (NHW * NC);
    uint4 u = *(const uint4*)(g_xalh + e);
    float2 f0 = h2f2(u.x), f1 = h2f2(u.y), f2 = h2f2(u.z), f3 = h2f2(u.w);
    const float4 sa0 = *reinterpret_cast<const float4*>(&g_sa[b * NHW + p]);
    const float4 sa1 = *reinterpret_cast<const float4*>(&g_sa[b * NHW + p + 4]);
    const float cc = g_ca[b * NC + c];
    float4 r0, r1;
    r0.x = f0.x * sa0.x * cc;  r0.y = f0.y * sa0.y * cc;
    r0.z = f1.x * sa0.z * cc;  r0.w = f1.y * sa0.w * cc;
    r1.x = f2.x * sa1.x * cc;  r1.y = f2.y * sa1.y * cc;
    r1.z = f3.x * sa1.z * cc;  r1.w = f3.y * sa1.w * cc;
    *reinterpret_cast<float4*>(&out[e]) = r0;
    *reinterpret_cast<float4*>(&out[e + 4]) = r1;
}

// ---------------------------------------------------------------------------
extern "C" void kernel_launch(void* const* d_in, const int* in_sizes, int n_in,
                              void* d_out, int out_size) {
    const float* x       = (const float*)d_in[0];
    const float* align_w = (const float*)d_in[1];
    const float* align_g = (const float*)d_in[2];
    const float* align_b = (const float*)d_in[3];
    const float* align_m = (const float*)d_in[4];
    const float* align_v = (const float*)d_in[5];
    const float* mlp_w1  = (const float*)d_in[6];
    const float* mlp_w2  = (const float*)d_in[7];
    const float* loc_w1  = (const float*)d_in[8];
    const float* loc_w2  = (const float*)d_in[9];
    const float* fusion  = (const float*)d_in[10];
    const float* off_w1  = (const float*)d_in[11];
    const float* off_g   = (const float*)d_in[12];
    const float* off_bt  = (const float*)d_in[13];
    const float* off_m   = (const float*)d_in[14];
    const float* off_v   = (const float*)d_in[15];
    const float* off_w2  = (const float*)d_in[16];
    const float* off_b2  = (const float*)d_in[17];
    const float* attn_w  = (const float*)d_in[18];
    float* out = (float*)d_out;

    wprep_kernel<<<129, 288>>>(align_w, align_g, align_b, align_m, align_v,
                               off_w2, off_b2);

    dim3 gGemm(NTILES, NB);
    gemm_kernel<<<gGemm, 256, DSMEM_U32 * 4>>>(x);

    pool_kernel<<<NB * NC, 160>>>();
    ca_kernel<<<NB, 256>>>(mlp_w1, mlp_w2, loc_w1, loc_w2, fusion);

    dim3 gSf(NHW / 8 / 128, NB);
    sf_kernel<<<gSf, 128>>>();

    dim3 gPix(NHW / 256, NB);
    dim3 gOff1(NHW / 256, 16, NB);
    off1_kernel<<<gOff1, 256>>>(off_w1, off_g, off_bt, off_m, off_v);
    off2_sample_kernel<<<gPix, 256>>>();
    sa_kernel<<<gPix, 256>>>(attn_w);

    const unsigned total8 = (unsigned)NB * NC * NHW / 8;
    final_kernel<<<(total8 + 255) / 256, 256>>>(out);
}